// round 6
// baseline (speedup 1.0000x reference)
#include <cuda_runtime.h>
#include <cuda_bf16.h>
#include <cstdint>

// Shapes (fixed by the problem):
//   x:     [4, 256, 64, 64]
//   h:     [4, 128, 64, 64]   (half-res; h_up = 2x nearest upsample of h)
//   wgt:   [4, 200, 64, 64]   (kernel-gen branch at HALF res: constant over 2x2)
//   out:   [4, 128, 128, 128]
#define B_     4
#define CIN    256
#define COUT   128
#define HHALF  64
#define PHALF  4096        // 64*64
#define CRED   32
#define GROUPS 8
#define GC_    16
#define KK     25          // 5x5
#define SPAN   200         // KK*GROUPS

// Scratch (device globals; allocation inside kernel_launch is forbidden)
__device__ float g_h  [(size_t)B_ * COUT * PHALF];   // 8.4 MB
__device__ float g_wgt[(size_t)B_ * SPAN * PHALF];   // 13.1 MB

// ---------------------------------------------------------------------------
// Kernel 1: h = conv1x1(x, w1x1) + b1x1      (per-b GEMM [128x256]@[256x4096])
// v4: BM=64 o, BN=64 px, BK=16, 256 threads, 4x4 microtile (both operands
// LDS.128 -> 16 FFMA / 2 LDS, same ratio as 8x8 but 4x the threads).
// Grid = 64 px-tiles x 2 o-tiles x 4 b = 512 CTAs -> ~28 warps/SM (43% occ).
// Double-buffered smem, register prefetch, 1 __syncthreads per K-step.
// ---------------------------------------------------------------------------
__global__ __launch_bounds__(256) void conv1_k(const float* __restrict__ x,
                                               const float* __restrict__ w,
                                               const float* __restrict__ bias) {
    __shared__ float xs[2][16][64];    // [buf][k][pixel]
    __shared__ float ws[2][16][68];    // [buf][k][o], stride 68 (17x16B) keeps rows aligned

    const int b      = blockIdx.z;
    const int o_base = blockIdx.y * 64;
    const int p0     = blockIdx.x * 64;
    const int tid = threadIdx.x;
    const int tx  = tid & 15;          // px lane: px = 4*tx
    const int ty  = tid >> 4;          // o  lane: o  = 4*ty

    const float* xb = x + (size_t)b * CIN * PHALF + p0;

    // loader indices (one float4 each per iter)
    const int lk  = tid >> 4;          // x: k row (0..15)
    const int lp4 = tid & 15;          // x: px quad (0..15)
    const int wq  = tid & 3;           // w: k quad (0..3)
    const int wo  = tid >> 2;          // w: local o (0..63)

    float acc[4][4];
#pragma unroll
    for (int i = 0; i < 4; i++)
#pragma unroll
        for (int j = 0; j < 4; j++) acc[i][j] = 0.f;

    // ---- preload tile 0 into buffer 0 ----
    {
        float4 xv = ((const float4*)(xb + (size_t)lk * PHALF))[lp4];
        ((float4*)&xs[0][lk][0])[lp4] = xv;
        float4 wv = *(const float4*)(w + (size_t)(o_base + wo) * CIN + 4 * wq);
        ws[0][4 * wq + 0][wo] = wv.x;
        ws[0][4 * wq + 1][wo] = wv.y;
        ws[0][4 * wq + 2][wo] = wv.z;
        ws[0][4 * wq + 3][wo] = wv.w;
    }
    __syncthreads();

    for (int it = 0; it < 16; ++it) {
        const int cur = it & 1;
        const int kc_next = (it + 1) * 16;

        // prefetch next K-tile into registers
        float4 xr, wr;
        if (it < 15) {
            xr = ((const float4*)(xb + (size_t)(kc_next + lk) * PHALF))[lp4];
            wr = *(const float4*)(w + (size_t)(o_base + wo) * CIN + kc_next + 4 * wq);
        }

        // compute on current buffer: 16 k x (2 LDS.128 + 16 FFMA)
#pragma unroll
        for (int k = 0; k < 16; k++) {
            float4 wv = *(const float4*)&ws[cur][k][4 * ty];
            float4 xv = *(const float4*)&xs[cur][k][4 * tx];
            acc[0][0] += wv.x * xv.x; acc[0][1] += wv.x * xv.y;
            acc[0][2] += wv.x * xv.z; acc[0][3] += wv.x * xv.w;
            acc[1][0] += wv.y * xv.x; acc[1][1] += wv.y * xv.y;
            acc[1][2] += wv.y * xv.z; acc[1][3] += wv.y * xv.w;
            acc[2][0] += wv.z * xv.x; acc[2][1] += wv.z * xv.y;
            acc[2][2] += wv.z * xv.z; acc[2][3] += wv.z * xv.w;
            acc[3][0] += wv.w * xv.x; acc[3][1] += wv.w * xv.y;
            acc[3][2] += wv.w * xv.z; acc[3][3] += wv.w * xv.w;
        }

        // commit prefetched tile to the other buffer
        if (it < 15) {
            const int nxt = cur ^ 1;
            ((float4*)&xs[nxt][lk][0])[lp4] = xr;
            ws[nxt][4 * wq + 0][wo] = wr.x;
            ws[nxt][4 * wq + 1][wo] = wr.y;
            ws[nxt][4 * wq + 2][wo] = wr.z;
            ws[nxt][4 * wq + 3][wo] = wr.w;
        }
        __syncthreads();
    }

    // epilogue: bias + float4 stores (coalesced: 16 lanes x 16B = 256B per o)
#pragma unroll
    for (int i = 0; i < 4; i++) {
        int o = o_base + 4 * ty + i;
        float bv = bias[o];
        float4 v = make_float4(acc[i][0] + bv, acc[i][1] + bv,
                               acc[i][2] + bv, acc[i][3] + bv);
        *(float4*)(g_h + ((size_t)b * COUT + o) * PHALF + p0 + 4 * tx) = v;
    }
}

// ---------------------------------------------------------------------------
// Kernel 2: kernel-generation branch AT HALF RES.
//   r   = relu(bn(w_red @ h + b_red))         [4, 32, 64, 64]
//   wgt = w_span @ r + b_span                 [4, 200, 64, 64]
// Block = 64 pixels, 256 threads -> grid 256.
// Stage 2: each thread computes 4 span rows (s, s+50, s+100, s+150) sharing
// one r_sh read -> 128 FMA per 32 LDS.
// ---------------------------------------------------------------------------
__global__ __launch_bounds__(256) void kgen_k(const float* __restrict__ wred,
                                              const float* __restrict__ bred,
                                              const float* __restrict__ gamma,
                                              const float* __restrict__ beta,
                                              const float* __restrict__ mean,
                                              const float* __restrict__ var,
                                              const float* __restrict__ wspan,
                                              const float* __restrict__ bspan) {
    __shared__ float pool[6400];        // stage1: wredT[4096] + h_sh[1024]; stage2: wspan[6400]
    __shared__ float r_sh[CRED][65];    // [o][p] padded

    const int tid = threadIdx.x;
    const int q0  = blockIdx.x * 64;    // global half-pixel id (b*4096 + p)
    const int b   = q0 >> 12;
    const int p0  = q0 & 4095;

    // wred transposed: pool[c*32 + o] = wred[o*128 + c]
    for (int i = tid; i < CRED * COUT; i += 256) {
        int o = i >> 7, c = i & 127;
        pool[c * CRED + o] = wred[i];
    }

    const int o  = tid & 31;      // r-channel this thread owns
    const int pg = tid >> 5;      // pixel slice (8 pixels)

    float racc[8];
    {
        float bv = bred[o];
#pragma unroll
        for (int pp = 0; pp < 8; pp++) racc[pp] = bv;
    }

    const float* hb = g_h + (size_t)b * COUT * PHALF + p0;
    float* h_sh = pool + 4096;    // [16][64]

    for (int cc = 0; cc < COUT; cc += 16) {
        __syncthreads();
        for (int i = tid; i < 16 * 64; i += 256) {
            int c = i >> 6, p = i & 63;
            h_sh[c * 64 + p] = hb[(size_t)(cc + c) * PHALF + p];
        }
        __syncthreads();
#pragma unroll
        for (int c = 0; c < 16; c++) {
            float wv = pool[(cc + c) * CRED + o];
#pragma unroll
            for (int pp = 0; pp < 8; pp++)
                racc[pp] += wv * h_sh[c * 64 + pg * 8 + pp];
        }
    }

    // BN + ReLU -> r_sh
    {
        float sc = gamma[o] * rsqrtf(var[o] + 1e-5f);
        float sh = beta[o] - mean[o] * sc;
#pragma unroll
        for (int pp = 0; pp < 8; pp++) {
            float v = racc[pp] * sc + sh;
            r_sh[o][pg * 8 + pp] = fmaxf(v, 0.f);
        }
    }
    __syncthreads();

    // stage 2: wspan into pool (overwrites stage-1 data)
    for (int i = tid; i < SPAN * CRED; i += 256) pool[i] = wspan[i];
    __syncthreads();

    float* wb = g_wgt + (size_t)b * SPAN * PHALF + p0;
    for (int idx = tid; idx < 50 * 64; idx += 256) {
        int s0 = idx >> 6, p = idx & 63;          // s0 in [0,50), uniform per warp
        float v0 = bspan[s0];
        float v1 = bspan[s0 + 50];
        float v2 = bspan[s0 + 100];
        float v3 = bspan[s0 + 150];
        const float* w0 = pool + (s0      ) * CRED;
        const float* w1 = pool + (s0 +  50) * CRED;
        const float* w2 = pool + (s0 + 100) * CRED;
        const float* w3 = pool + (s0 + 150) * CRED;
#pragma unroll
        for (int oo = 0; oo < CRED; oo++) {
            float r = r_sh[oo][p];
            v0 += w0[oo] * r;
            v1 += w1[oo] * r;
            v2 += w2[oo] * r;
            v3 += w3[oo] * r;
        }
        wb[(size_t)(s0      ) * PHALF + p] = v0;
        wb[(size_t)(s0 +  50) * PHALF + p] = v1;
        wb[(size_t)(s0 + 100) * PHALF + p] = v2;
        wb[(size_t)(s0 + 150) * PHALF + p] = v3;
    }
}

// ---------------------------------------------------------------------------
// Kernel 3: involution at full res.
// out[b, g*16+c, y, x] = sum_{kh,kw} wgt[b, g*25+kh*5+kw, y/2, x/2]
//                                    * h[b, g*16+c, (y+kh-2)/2, (x+kw-2)/2]
// Block: (b, g, 16x16 half-pixel tile). Thread = one half-pixel -> 2x2 outputs
// for all 16 group channels. 3x3 half-res neighborhood per channel.
// ---------------------------------------------------------------------------
__global__ __launch_bounds__(256) void inv_k(float* __restrict__ out) {
    __shared__ float hs[GC_][18][19];   // halo'd h tile, ~21.4 KB

    const int b = blockIdx.z;
    const int g = blockIdx.y;
    const int ti = (blockIdx.x >> 2) * 16;
    const int tj = (blockIdx.x & 3) * 16;
    const int tid = threadIdx.x;

    // load h tile (+1 halo each side) with zero pad
    const float* hb = g_h + ((size_t)b * COUT + g * GC_) * PHALF;
    for (int e = tid; e < GC_ * 18 * 18; e += 256) {
        int c   = e / 324;
        int rem = e - c * 324;
        int rr  = rem / 18, cc = rem - rr * 18;
        int gi = ti - 1 + rr, gj = tj - 1 + cc;
        float v = 0.f;
        if ((unsigned)gi < 64u && (unsigned)gj < 64u)
            v = hb[(size_t)c * PHALF + gi * HHALF + gj];
        hs[c][rr][cc] = v;
    }

    const int jl = tid & 15, il = tid >> 4;
    const int pix = (ti + il) * HHALF + (tj + jl);

    // 25 involution weights for this half-pixel (coalesced loads)
    float wk[KK];
    const float* wgp = g_wgt + ((size_t)b * SPAN + g * KK) * PHALF + pix;
#pragma unroll
    for (int k = 0; k < KK; k++) wk[k] = wgp[(size_t)k * PHALF];

    __syncthreads();

    // half-res row/col offset tables: index into 3x3 neighborhood (0..2)
    const int R0[5] = {0, 0, 1, 1, 2};
    const int R1[5] = {0, 1, 1, 2, 2};

    const int y0 = 2 * (ti + il), x0 = 2 * (tj + jl);
    float* ob = out + (((size_t)b * COUT + g * GC_) * 128 + y0) * 128 + x0;

#pragma unroll
    for (int c = 0; c < GC_; c++) {
        float n[3][3];
#pragma unroll
        for (int a = 0; a < 3; a++)
#pragma unroll
            for (int d = 0; d < 3; d++)
                n[a][d] = hs[c][il + a][jl + d];

        float a00 = 0.f, a01 = 0.f, a10 = 0.f, a11 = 0.f;
#pragma unroll
        for (int kh = 0; kh < 5; kh++) {
            const int r0 = R0[kh], r1 = R1[kh];
#pragma unroll
            for (int kw = 0; kw < 5; kw++) {
                const float wv = wk[kh * 5 + kw];
                const int c0 = R0[kw], c1 = R1[kw];
                a00 += wv * n[r0][c0];
                a01 += wv * n[r0][c1];
                a10 += wv * n[r1][c0];
                a11 += wv * n[r1][c1];
            }
        }
        float2 v0 = make_float2(a00, a01);
        float2 v1 = make_float2(a10, a11);
        *reinterpret_cast<float2*>(ob + (size_t)c * 16384)       = v0;
        *reinterpret_cast<float2*>(ob + (size_t)c * 16384 + 128) = v1;
    }
}

// ---------------------------------------------------------------------------
extern "C" void kernel_launch(void* const* d_in, const int* in_sizes, int n_in,
                              void* d_out, int out_size) {
    const float* x      = (const float*)d_in[0];
    const float* w1x1   = (const float*)d_in[1];
    const float* b1x1   = (const float*)d_in[2];
    const float* w_red  = (const float*)d_in[3];
    const float* b_red  = (const float*)d_in[4];
    const float* gamma  = (const float*)d_in[5];
    const float* beta   = (const float*)d_in[6];
    const float* mean   = (const float*)d_in[7];
    const float* var    = (const float*)d_in[8];
    const float* w_span = (const float*)d_in[9];
    const float* b_span = (const float*)d_in[10];
    float* out = (float*)d_out;

    conv1_k<<<dim3(PHALF / 64, 2, B_), 256>>>(x, w1x1, b1x1);
    kgen_k<<<dim3((B_ * PHALF) / 64, 1, 1), 256>>>(w_red, b_red, gamma, beta,
                                                   mean, var, w_span, b_span);
    inv_k<<<dim3(16, GROUPS, B_), 256>>>(out);
}

// round 7
// speedup vs baseline: 1.1731x; 1.1731x over previous
#include <cuda_runtime.h>
#include <cuda_bf16.h>
#include <cstdint>

// Shapes (fixed by the problem):
//   x:     [4, 256, 64, 64]
//   h:     [4, 128, 64, 64]   (half-res; h_up = 2x nearest upsample of h)
//   wgt:   [4, 200, 64, 64]   (kernel-gen branch at HALF res: constant over 2x2)
//   out:   [4, 128, 128, 128]
#define B_     4
#define CIN    256
#define COUT   128
#define HHALF  64
#define PHALF  4096        // 64*64
#define CRED   32
#define GROUPS 8
#define GC_    16
#define KK     25          // 5x5
#define SPAN   200         // KK*GROUPS

// Scratch (device globals; allocation inside kernel_launch is forbidden)
__device__ float g_h  [(size_t)B_ * COUT * PHALF];   // 8.4 MB
__device__ float g_wgt[(size_t)B_ * SPAN * PHALF];   // 13.1 MB

// ---------------------------------------------------------------------------
// Kernel 1: h = conv1x1(x, w1x1) + b1x1   (R5 config: ~95% of fp32 FFMA roof)
// BM=64 o, BN=128 px, BK=16, 256 threads, 4(o)x8(px) microtile.
// Double-buffered smem, register prefetch, 1 __syncthreads per K-step.
// ---------------------------------------------------------------------------
__global__ __launch_bounds__(256) void conv1_k(const float* __restrict__ x,
                                               const float* __restrict__ w,
                                               const float* __restrict__ bias) {
    __shared__ float xs[2][16][128];   // [buf][k][pixel]
    __shared__ float ws[2][16][68];    // [buf][k][o], stride 68 keeps rows 16B-aligned

    const int b      = blockIdx.z;
    const int o_base = blockIdx.y * 64;
    const int p0     = blockIdx.x * 128;
    const int tid = threadIdx.x;
    const int tx  = tid & 15;          // pixel lane
    const int ty  = tid >> 4;          // o lane

    const float* xb = x + (size_t)b * CIN * PHALF + p0;

    const int wq = tid & 3;            // k-quad
    const int wo = tid >> 2;           // local o (0..63)

    float acc[4][8];
#pragma unroll
    for (int i = 0; i < 4; i++)
#pragma unroll
        for (int j = 0; j < 8; j++) acc[i][j] = 0.f;

    // ---- preload tile 0 directly into smem[0] ----
    {
#pragma unroll
        for (int q = 0; q < 2; q++) {
            int f = tid + 256 * q;
            int k = f >> 5, pp4 = f & 31;
            float4 v = ((const float4*)(xb + (size_t)k * PHALF))[pp4];
            ((float4*)&xs[0][k][0])[pp4] = v;
        }
        float4 wv = *(const float4*)(w + (size_t)(o_base + wo) * CIN + 4 * wq);
        ws[0][4 * wq + 0][wo] = wv.x;
        ws[0][4 * wq + 1][wo] = wv.y;
        ws[0][4 * wq + 2][wo] = wv.z;
        ws[0][4 * wq + 3][wo] = wv.w;
    }
    __syncthreads();

    for (int it = 0; it < 16; ++it) {
        const int cur = it & 1;
        const int kc_next = (it + 1) * 16;

        float4 xr[2], wr;
        if (it < 15) {
#pragma unroll
            for (int q = 0; q < 2; q++) {
                int f = tid + 256 * q;
                int k = f >> 5, pp4 = f & 31;
                xr[q] = ((const float4*)(xb + (size_t)(kc_next + k) * PHALF))[pp4];
            }
            wr = *(const float4*)(w + (size_t)(o_base + wo) * CIN + kc_next + 4 * wq);
        }

#pragma unroll
        for (int k = 0; k < 16; k++) {
            float4 wv = *(const float4*)&ws[cur][k][4 * ty];
            float2 xv[4];
#pragma unroll
            for (int g = 0; g < 4; g++)
                xv[g] = *(const float2*)&xs[cur][k][2 * tx + 32 * g];

            float wa0 = wv.x, wa1 = wv.y, wa2 = wv.z, wa3 = wv.w;
#pragma unroll
            for (int g = 0; g < 4; g++) {
                acc[0][2*g]   += wa0 * xv[g].x;  acc[0][2*g+1] += wa0 * xv[g].y;
                acc[1][2*g]   += wa1 * xv[g].x;  acc[1][2*g+1] += wa1 * xv[g].y;
                acc[2][2*g]   += wa2 * xv[g].x;  acc[2][2*g+1] += wa2 * xv[g].y;
                acc[3][2*g]   += wa3 * xv[g].x;  acc[3][2*g+1] += wa3 * xv[g].y;
            }
        }

        if (it < 15) {
            const int nxt = cur ^ 1;
#pragma unroll
            for (int q = 0; q < 2; q++) {
                int f = tid + 256 * q;
                int k = f >> 5, pp4 = f & 31;
                ((float4*)&xs[nxt][k][0])[pp4] = xr[q];
            }
            ws[nxt][4 * wq + 0][wo] = wr.x;
            ws[nxt][4 * wq + 1][wo] = wr.y;
            ws[nxt][4 * wq + 2][wo] = wr.z;
            ws[nxt][4 * wq + 3][wo] = wr.w;
        }
        __syncthreads();
    }

#pragma unroll
    for (int ii = 0; ii < 4; ii++) {
        int o = o_base + 4 * ty + ii;
        float bv = bias[o];
        float* op = g_h + ((size_t)b * COUT + o) * PHALF + p0;
#pragma unroll
        for (int g = 0; g < 4; g++) {
            float2 v = make_float2(acc[ii][2*g] + bv, acc[ii][2*g+1] + bv);
            *(float2*)(op + 2 * tx + 32 * g) = v;
        }
    }
}

// ---------------------------------------------------------------------------
// Kernel 2 (v2): kernel-generation branch AT HALF RES. Block = 64 px, 256 thr.
//   Stage 1: r = relu(bn(w_red @ h + b_red)), microtile 4o x 2px:
//            w via warp-uniform broadcast LDS.128, h via LDS.64.
//   Stage 2: wgt = w_span @ r + b_span, microtile 8s x 8px:
//            wspan rows padded to 33 floats (conflict-free scalar broadcast),
//            r rows padded to 68 floats (aligned float4 reads).
// ---------------------------------------------------------------------------
__global__ __launch_bounds__(256) void kgen_k(const float* __restrict__ wred,
                                              const float* __restrict__ bred,
                                              const float* __restrict__ gamma,
                                              const float* __restrict__ beta,
                                              const float* __restrict__ mean,
                                              const float* __restrict__ var,
                                              const float* __restrict__ wspan,
                                              const float* __restrict__ bspan) {
    __shared__ float pool[6600];        // stage1: wredT[4096]; stage2: wspan padded [200][33]
    __shared__ float h_sh[16][64];      // h chunk
    __shared__ float r_sh[CRED][68];    // [o][px], rows 16B-aligned (68*4=272=17*16)

    const int tid = threadIdx.x;
    const int q0  = blockIdx.x * 64;    // global half-pixel id (b*4096 + p)
    const int b   = q0 >> 12;
    const int p0  = q0 & 4095;

    // wred transposed: pool[c*32 + o] = wred[o*128 + c]
    for (int i = tid; i < CRED * COUT; i += 256) {
        int o = i >> 7, c = i & 127;
        pool[c * CRED + o] = wred[i];
    }

    // ---- stage 1: thread = (oq warp-uniform, pxp) -> 4 o x 2 px ----
    const int oq  = tid >> 5;          // 0..7, warp-uniform -> w reads broadcast
    const int pxp = tid & 31;          // px pair: px = 2*pxp

    float acc[4][2];
    {
#pragma unroll
        for (int i = 0; i < 4; i++) {
            float bv = bred[4 * oq + i];
            acc[i][0] = bv; acc[i][1] = bv;
        }
    }

    const float* hb = g_h + (size_t)b * COUT * PHALF + p0;
    const int hc = tid >> 4, hp4 = tid & 15;   // h loader: one float4 each

    for (int cc = 0; cc < COUT; cc += 16) {
        __syncthreads();
        *(float4*)&h_sh[hc][4 * hp4] =
            *(const float4*)(hb + (size_t)(cc + hc) * PHALF + 4 * hp4);
        __syncthreads();
#pragma unroll
        for (int c = 0; c < 16; c++) {
            float4 wv = *(const float4*)&pool[(cc + c) * CRED + 4 * oq];  // broadcast
            float2 hv = *(const float2*)&h_sh[c][2 * pxp];
            acc[0][0] += wv.x * hv.x;  acc[0][1] += wv.x * hv.y;
            acc[1][0] += wv.y * hv.x;  acc[1][1] += wv.y * hv.y;
            acc[2][0] += wv.z * hv.x;  acc[2][1] += wv.z * hv.y;
            acc[3][0] += wv.w * hv.x;  acc[3][1] += wv.w * hv.y;
        }
    }

    // BN + ReLU -> r_sh (float2 stores)
#pragma unroll
    for (int i = 0; i < 4; i++) {
        int o = 4 * oq + i;
        float sc = gamma[o] * rsqrtf(var[o] + 1e-5f);
        float sh = beta[o] - mean[o] * sc;
        float v0 = fmaxf(acc[i][0] * sc + sh, 0.f);
        float v1 = fmaxf(acc[i][1] * sc + sh, 0.f);
        *(float2*)&r_sh[o][2 * pxp] = make_float2(v0, v1);
    }
    __syncthreads();

    // ---- stage 2: wspan into pool with row pad 33 (banks decorrelated) ----
    for (int i = tid; i < SPAN * CRED; i += 256) {
        int s = i >> 5, oo = i & 31;
        pool[s * 33 + oo] = wspan[i];
    }
    __syncthreads();

    // thread = (s8, p8): 8 s-rows x 8 px.  25*8 = 200 active threads.
    if (tid < 200) {
        const int s0 = (tid >> 3) * 8;     // 0,8,...,192
        const int px = (tid & 7) * 8;      // 0..56

        float acc2[8][8];
#pragma unroll
        for (int i = 0; i < 8; i++) {
            float bv = bspan[s0 + i];
#pragma unroll
            for (int j = 0; j < 8; j++) acc2[i][j] = bv;
        }

#pragma unroll 4
        for (int oo = 0; oo < CRED; oo++) {
            float w8[8];
#pragma unroll
            for (int i = 0; i < 8; i++) w8[i] = pool[(s0 + i) * 33 + oo];
            float4 ra = *(const float4*)&r_sh[oo][px];
            float4 rb = *(const float4*)&r_sh[oo][px + 4];
#pragma unroll
            for (int i = 0; i < 8; i++) {
                acc2[i][0] += w8[i] * ra.x;  acc2[i][1] += w8[i] * ra.y;
                acc2[i][2] += w8[i] * ra.z;  acc2[i][3] += w8[i] * ra.w;
                acc2[i][4] += w8[i] * rb.x;  acc2[i][5] += w8[i] * rb.y;
                acc2[i][6] += w8[i] * rb.z;  acc2[i][7] += w8[i] * rb.w;
            }
        }

        float* wb = g_wgt + (size_t)b * SPAN * PHALF + p0 + px;
#pragma unroll
        for (int i = 0; i < 8; i++) {
            float4 v0 = make_float4(acc2[i][0], acc2[i][1], acc2[i][2], acc2[i][3]);
            float4 v1 = make_float4(acc2[i][4], acc2[i][5], acc2[i][6], acc2[i][7]);
            *(float4*)(wb + (size_t)(s0 + i) * PHALF)     = v0;
            *(float4*)(wb + (size_t)(s0 + i) * PHALF + 4) = v1;
        }
    }
}

// ---------------------------------------------------------------------------
// Kernel 3: involution at full res (unchanged).
// out[b, g*16+c, y, x] = sum_{kh,kw} wgt[b, g*25+kh*5+kw, y/2, x/2]
//                                    * h[b, g*16+c, (y+kh-2)/2, (x+kw-2)/2]
// ---------------------------------------------------------------------------
__global__ __launch_bounds__(256) void inv_k(float* __restrict__ out) {
    __shared__ float hs[GC_][18][19];   // halo'd h tile, ~21.4 KB

    const int b = blockIdx.z;
    const int g = blockIdx.y;
    const int ti = (blockIdx.x >> 2) * 16;
    const int tj = (blockIdx.x & 3) * 16;
    const int tid = threadIdx.x;

    const float* hb = g_h + ((size_t)b * COUT + g * GC_) * PHALF;
    for (int e = tid; e < GC_ * 18 * 18; e += 256) {
        int c   = e / 324;
        int rem = e - c * 324;
        int rr  = rem / 18, cc = rem - rr * 18;
        int gi = ti - 1 + rr, gj = tj - 1 + cc;
        float v = 0.f;
        if ((unsigned)gi < 64u && (unsigned)gj < 64u)
            v = hb[(size_t)c * PHALF + gi * HHALF + gj];
        hs[c][rr][cc] = v;
    }

    const int jl = tid & 15, il = tid >> 4;
    const int pix = (ti + il) * HHALF + (tj + jl);

    float wk[KK];
    const float* wgp = g_wgt + ((size_t)b * SPAN + g * KK) * PHALF + pix;
#pragma unroll
    for (int k = 0; k < KK; k++) wk[k] = wgp[(size_t)k * PHALF];

    __syncthreads();

    const int R0[5] = {0, 0, 1, 1, 2};
    const int R1[5] = {0, 1, 1, 2, 2};

    const int y0 = 2 * (ti + il), x0 = 2 * (tj + jl);
    float* ob = out + (((size_t)b * COUT + g * GC_) * 128 + y0) * 128 + x0;

#pragma unroll
    for (int c = 0; c < GC_; c++) {
        float n[3][3];
#pragma unroll
        for (int a = 0; a < 3; a++)
#pragma unroll
            for (int d = 0; d < 3; d++)
                n[a][d] = hs[c][il + a][jl + d];

        float a00 = 0.f, a01 = 0.f, a10 = 0.f, a11 = 0.f;
#pragma unroll
        for (int kh = 0; kh < 5; kh++) {
            const int r0 = R0[kh], r1 = R1[kh];
#pragma unroll
            for (int kw = 0; kw < 5; kw++) {
                const float wv = wk[kh * 5 + kw];
                const int c0 = R0[kw], c1 = R1[kw];
                a00 += wv * n[r0][c0];
                a01 += wv * n[r0][c1];
                a10 += wv * n[r1][c0];
                a11 += wv * n[r1][c1];
            }
        }
        float2 v0 = make_float2(a00, a01);
        float2 v1 = make_float2(a10, a11);
        *reinterpret_cast<float2*>(ob + (size_t)c * 16384)       = v0;
        *reinterpret_cast<float2*>(ob + (size_t)c * 16384 + 128) = v1;
    }
}

// ---------------------------------------------------------------------------
extern "C" void kernel_launch(void* const* d_in, const int* in_sizes, int n_in,
                              void* d_out, int out_size) {
    const float* x      = (const float*)d_in[0];
    const float* w1x1   = (const float*)d_in[1];
    const float* b1x1   = (const float*)d_in[2];
    const float* w_red  = (const float*)d_in[3];
    const float* b_red  = (const float*)d_in[4];
    const float* gamma  = (const float*)d_in[5];
    const float* beta   = (const float*)d_in[6];
    const float* mean   = (const float*)d_in[7];
    const float* var    = (const float*)d_in[8];
    const float* w_span = (const float*)d_in[9];
    const float* b_span = (const float*)d_in[10];
    float* out = (float*)d_out;

    conv1_k<<<dim3(PHALF / 128, 2, B_), 256>>>(x, w1x1, b1x1);
    kgen_k<<<dim3((B_ * PHALF) / 64, 1, 1), 256>>>(w_red, b_red, gamma, beta,
                                                   mean, var, w_span, b_span);
    inv_k<<<dim3(16, GROUPS, B_), 256>>>(out);
}

// round 8
// speedup vs baseline: 1.2222x; 1.0418x over previous
#include <cuda_runtime.h>
#include <cuda_bf16.h>
#include <cstdint>

// Shapes (fixed by the problem):
//   x:     [4, 256, 64, 64]
//   h:     [4, 128, 64, 64]   (half-res; h_up = 2x nearest upsample of h)
//   wgt:   [4, 200, 64, 64]   (kernel-gen branch at HALF res: constant over 2x2)
//   out:   [4, 128, 128, 128]
#define B_     4
#define CIN    256
#define COUT   128
#define HHALF  64
#define PHALF  4096        // 64*64
#define CRED   32
#define GROUPS 8
#define GC_    16
#define KK     25          // 5x5
#define SPAN   200         // KK*GROUPS

// Scratch (device globals; allocation inside kernel_launch is forbidden)
__device__ float g_h  [(size_t)B_ * COUT * PHALF];   // 8.4 MB
__device__ float g_wgt[(size_t)B_ * SPAN * PHALF];   // 13.1 MB

// ---- packed f32x2 helpers (sm_100+; per-lane identical to fmaf) ------------
__device__ __forceinline__ unsigned long long pk2(float a, float b) {
    unsigned long long r;
    asm("mov.b64 %0, {%1, %2};" : "=l"(r) : "f"(a), "f"(b));
    return r;
}
__device__ __forceinline__ void fma2(unsigned long long& d,
                                     unsigned long long a, unsigned long long b) {
    asm("fma.rn.f32x2 %0, %1, %2, %0;" : "+l"(d) : "l"(a), "l"(b));
}
__device__ __forceinline__ void upk2(unsigned long long v, float& lo, float& hi) {
    asm("mov.b64 {%0, %1}, %2;" : "=f"(lo), "=f"(hi) : "l"(v));
}

// ---------------------------------------------------------------------------
// Kernel 1: h = conv1x1(x, w1x1) + b1x1    (per-b GEMM [128x256]@[256x4096])
// BM=64 o, BN=128 px, BK=16, 256 threads, 4(o)x8(px) microtile, accumulators
// held as 4x4 packed f32x2 pairs -> 16 fma.f32x2 per k-step (vs 32 FFMA).
// Double-buffered smem, register prefetch, 1 __syncthreads per K-step.
// ---------------------------------------------------------------------------
__global__ __launch_bounds__(256) void conv1_k(const float* __restrict__ x,
                                               const float* __restrict__ w,
                                               const float* __restrict__ bias) {
    __shared__ float xs[2][16][128];   // [buf][k][pixel]
    __shared__ float ws[2][16][68];    // [buf][k][o], stride 68 keeps rows 16B-aligned

    const int b      = blockIdx.z;
    const int o_base = blockIdx.y * 64;
    const int p0     = blockIdx.x * 128;
    const int tid = threadIdx.x;
    const int tx  = tid & 15;          // pixel lane: px {4tx..4tx+3} and {64+4tx..+3}
    const int ty  = tid >> 4;          // o lane: o = 4*ty + i

    const float* xb = x + (size_t)b * CIN * PHALF + p0;

    const int wq = tid & 3;            // k-quad
    const int wo = tid >> 2;           // local o (0..63)

    unsigned long long acc[4][4];      // [o][px-pair]
#pragma unroll
    for (int i = 0; i < 4; i++)
#pragma unroll
        for (int j = 0; j < 4; j++) acc[i][j] = 0ull;

    // ---- preload tile 0 directly into smem[0] ----
    {
#pragma unroll
        for (int q = 0; q < 2; q++) {
            int f = tid + 256 * q;
            int k = f >> 5, pp4 = f & 31;
            float4 v = ((const float4*)(xb + (size_t)k * PHALF))[pp4];
            ((float4*)&xs[0][k][0])[pp4] = v;
        }
        float4 wv = *(const float4*)(w + (size_t)(o_base + wo) * CIN + 4 * wq);
        ws[0][4 * wq + 0][wo] = wv.x;
        ws[0][4 * wq + 1][wo] = wv.y;
        ws[0][4 * wq + 2][wo] = wv.z;
        ws[0][4 * wq + 3][wo] = wv.w;
    }
    __syncthreads();

    for (int it = 0; it < 16; ++it) {
        const int cur = it & 1;
        const int kc_next = (it + 1) * 16;

        float4 xr[2], wr;
        if (it < 15) {
#pragma unroll
            for (int q = 0; q < 2; q++) {
                int f = tid + 256 * q;
                int k = f >> 5, pp4 = f & 31;
                xr[q] = ((const float4*)(xb + (size_t)(kc_next + k) * PHALF))[pp4];
            }
            wr = *(const float4*)(w + (size_t)(o_base + wo) * CIN + kc_next + 4 * wq);
        }

#pragma unroll
        for (int k = 0; k < 16; k++) {
            float4 wv = *(const float4*)&ws[cur][k][4 * ty];
            ulonglong2 xa = *(const ulonglong2*)&xs[cur][k][4 * tx];        // pairs 0,1
            ulonglong2 xb2 = *(const ulonglong2*)&xs[cur][k][64 + 4 * tx];  // pairs 2,3

            unsigned long long w0 = pk2(wv.x, wv.x);
            unsigned long long w1 = pk2(wv.y, wv.y);
            unsigned long long w2 = pk2(wv.z, wv.z);
            unsigned long long w3 = pk2(wv.w, wv.w);

            fma2(acc[0][0], w0, xa.x); fma2(acc[0][1], w0, xa.y);
            fma2(acc[0][2], w0, xb2.x); fma2(acc[0][3], w0, xb2.y);
            fma2(acc[1][0], w1, xa.x); fma2(acc[1][1], w1, xa.y);
            fma2(acc[1][2], w1, xb2.x); fma2(acc[1][3], w1, xb2.y);
            fma2(acc[2][0], w2, xa.x); fma2(acc[2][1], w2, xa.y);
            fma2(acc[2][2], w2, xb2.x); fma2(acc[2][3], w2, xb2.y);
            fma2(acc[3][0], w3, xa.x); fma2(acc[3][1], w3, xa.y);
            fma2(acc[3][2], w3, xb2.x); fma2(acc[3][3], w3, xb2.y);
        }

        if (it < 15) {
            const int nxt = cur ^ 1;
#pragma unroll
            for (int q = 0; q < 2; q++) {
                int f = tid + 256 * q;
                int k = f >> 5, pp4 = f & 31;
                ((float4*)&xs[nxt][k][0])[pp4] = xr[q];
            }
            ws[nxt][4 * wq + 0][wo] = wr.x;
            ws[nxt][4 * wq + 1][wo] = wr.y;
            ws[nxt][4 * wq + 2][wo] = wr.z;
            ws[nxt][4 * wq + 3][wo] = wr.w;
        }
        __syncthreads();
    }

    // epilogue: unpack + bias + float4 stores (coalesced)
#pragma unroll
    for (int i = 0; i < 4; i++) {
        int o = o_base + 4 * ty + i;
        float bv = bias[o];
        float l0, h0, l1, h1, l2, h2, l3, h3;
        upk2(acc[i][0], l0, h0); upk2(acc[i][1], l1, h1);
        upk2(acc[i][2], l2, h2); upk2(acc[i][3], l3, h3);
        float* op = g_h + ((size_t)b * COUT + o) * PHALF + p0;
        *(float4*)(op + 4 * tx)      = make_float4(l0 + bv, h0 + bv, l1 + bv, h1 + bv);
        *(float4*)(op + 64 + 4 * tx) = make_float4(l2 + bv, h2 + bv, l3 + bv, h3 + bv);
    }
}

// ---------------------------------------------------------------------------
// Kernel 2: kernel-generation branch AT HALF RES. Block = 64 px, 256 thr.
//   Stage 1: r = relu(bn(w_red @ h + b_red)), microtile 4o x 2px:
//            w via warp-uniform broadcast LDS.128, h via LDS.64.
//   Stage 2: wgt = w_span @ r + b_span, microtile 8s x 8px:
//            wspan rows padded to 33 floats (conflict-free scalar broadcast),
//            r rows padded to 68 floats (aligned float4 reads).
// ---------------------------------------------------------------------------
__global__ __launch_bounds__(256) void kgen_k(const float* __restrict__ wred,
                                              const float* __restrict__ bred,
                                              const float* __restrict__ gamma,
                                              const float* __restrict__ beta,
                                              const float* __restrict__ mean,
                                              const float* __restrict__ var,
                                              const float* __restrict__ wspan,
                                              const float* __restrict__ bspan) {
    __shared__ float pool[6600];        // stage1: wredT[4096]; stage2: wspan padded [200][33]
    __shared__ float h_sh[16][64];      // h chunk
    __shared__ float r_sh[CRED][68];    // [o][px], rows 16B-aligned

    const int tid = threadIdx.x;
    const int q0  = blockIdx.x * 64;    // global half-pixel id (b*4096 + p)
    const int b   = q0 >> 12;
    const int p0  = q0 & 4095;

    // wred transposed: pool[c*32 + o] = wred[o*128 + c]
    for (int i = tid; i < CRED * COUT; i += 256) {
        int o = i >> 7, c = i & 127;
        pool[c * CRED + o] = wred[i];
    }

    // ---- stage 1: thread = (oq warp-uniform, pxp) -> 4 o x 2 px ----
    const int oq  = tid >> 5;          // 0..7, warp-uniform -> w reads broadcast
    const int pxp = tid & 31;          // px pair: px = 2*pxp

    float acc[4][2];
    {
#pragma unroll
        for (int i = 0; i < 4; i++) {
            float bv = bred[4 * oq + i];
            acc[i][0] = bv; acc[i][1] = bv;
        }
    }

    const float* hb = g_h + (size_t)b * COUT * PHALF + p0;
    const int hc = tid >> 4, hp4 = tid & 15;   // h loader: one float4 each

    for (int cc = 0; cc < COUT; cc += 16) {
        __syncthreads();
        *(float4*)&h_sh[hc][4 * hp4] =
            *(const float4*)(hb + (size_t)(cc + hc) * PHALF + 4 * hp4);
        __syncthreads();
#pragma unroll
        for (int c = 0; c < 16; c++) {
            float4 wv = *(const float4*)&pool[(cc + c) * CRED + 4 * oq];  // broadcast
            float2 hv = *(const float2*)&h_sh[c][2 * pxp];
            acc[0][0] += wv.x * hv.x;  acc[0][1] += wv.x * hv.y;
            acc[1][0] += wv.y * hv.x;  acc[1][1] += wv.y * hv.y;
            acc[2][0] += wv.z * hv.x;  acc[2][1] += wv.z * hv.y;
            acc[3][0] += wv.w * hv.x;  acc[3][1] += wv.w * hv.y;
        }
    }

    // BN + ReLU -> r_sh (float2 stores)
#pragma unroll
    for (int i = 0; i < 4; i++) {
        int o = 4 * oq + i;
        float sc = gamma[o] * rsqrtf(var[o] + 1e-5f);
        float sh = beta[o] - mean[o] * sc;
        float v0 = fmaxf(acc[i][0] * sc + sh, 0.f);
        float v1 = fmaxf(acc[i][1] * sc + sh, 0.f);
        *(float2*)&r_sh[o][2 * pxp] = make_float2(v0, v1);
    }
    __syncthreads();

    // ---- stage 2: wspan into pool with row pad 33 (banks decorrelated) ----
    for (int i = tid; i < SPAN * CRED; i += 256) {
        int s = i >> 5, oo = i & 31;
        pool[s * 33 + oo] = wspan[i];
    }
    __syncthreads();

    // thread = (s8, p8): 8 s-rows x 8 px.  25*8 = 200 active threads.
    if (tid < 200) {
        const int s0 = (tid >> 3) * 8;     // 0,8,...,192
        const int px = (tid & 7) * 8;      // 0..56

        float acc2[8][8];
#pragma unroll
        for (int i = 0; i < 8; i++) {
            float bv = bspan[s0 + i];
#pragma unroll
            for (int j = 0; j < 8; j++) acc2[i][j] = bv;
        }

#pragma unroll 4
        for (int oo = 0; oo < CRED; oo++) {
            float w8[8];
#pragma unroll
            for (int i = 0; i < 8; i++) w8[i] = pool[(s0 + i) * 33 + oo];
            float4 ra = *(const float4*)&r_sh[oo][px];
            float4 rb = *(const float4*)&r_sh[oo][px + 4];
#pragma unroll
            for (int i = 0; i < 8; i++) {
                acc2[i][0] += w8[i] * ra.x;  acc2[i][1] += w8[i] * ra.y;
                acc2[i][2] += w8[i] * ra.z;  acc2[i][3] += w8[i] * ra.w;
                acc2[i][4] += w8[i] * rb.x;  acc2[i][5] += w8[i] * rb.y;
                acc2[i][6] += w8[i] * rb.z;  acc2[i][7] += w8[i] * rb.w;
            }
        }

        float* wb = g_wgt + (size_t)b * SPAN * PHALF + p0 + px;
#pragma unroll
        for (int i = 0; i < 8; i++) {
            float4 v0 = make_float4(acc2[i][0], acc2[i][1], acc2[i][2], acc2[i][3]);
            float4 v1 = make_float4(acc2[i][4], acc2[i][5], acc2[i][6], acc2[i][7]);
            *(float4*)(wb + (size_t)(s0 + i) * PHALF)     = v0;
            *(float4*)(wb + (size_t)(s0 + i) * PHALF + 4) = v1;
        }
    }
}

// ---------------------------------------------------------------------------
// Kernel 3: involution at full res, packed f32x2 math.
// out[b, g*16+c, y, x] = sum_{kh,kw} wgt[b, g*25+kh*5+kw, y/2, x/2]
//                                    * h[b, g*16+c, (y+kh-2)/2, (x+kw-2)/2]
// Thread = one half-pixel -> 2x2 outputs x 16 channels. The (a00,a01) and
// (a10,a11) output pairs share weights and rows, so each becomes one f32x2
// accumulator fed by packed column-pairs: 50 fma2/channel vs 100 FFMA.
// ---------------------------------------------------------------------------
__global__ __launch_bounds__(256) void inv_k(float* __restrict__ out) {
    __shared__ float hs[GC_][18][19];   // halo'd h tile, ~21.4 KB

    const int b = blockIdx.z;
    const int g = blockIdx.y;
    const int ti = (blockIdx.x >> 2) * 16;
    const int tj = (blockIdx.x & 3) * 16;
    const int tid = threadIdx.x;

    const float* hb = g_h + ((size_t)b * COUT + g * GC_) * PHALF;
    for (int e = tid; e < GC_ * 18 * 18; e += 256) {
        int c   = e / 324;
        int rem = e - c * 324;
        int rr  = rem / 18, cc = rem - rr * 18;
        int gi = ti - 1 + rr, gj = tj - 1 + cc;
        float v = 0.f;
        if ((unsigned)gi < 64u && (unsigned)gj < 64u)
            v = hb[(size_t)c * PHALF + gi * HHALF + gj];
        hs[c][rr][cc] = v;
    }

    const int jl = tid & 15, il = tid >> 4;
    const int pix = (ti + il) * HHALF + (tj + jl);

    // 25 involution weights, packed to both f32x2 lanes (reused by 16 channels)
    unsigned long long wk2[KK];
    {
        const float* wgp = g_wgt + ((size_t)b * SPAN + g * KK) * PHALF + pix;
#pragma unroll
        for (int k = 0; k < KK; k++) {
            float wv = wgp[(size_t)k * PHALF];
            wk2[k] = pk2(wv, wv);
        }
    }

    __syncthreads();

    // column-pair index per kw: (R0[kw], R1[kw]) of the 3-wide neighborhood
    const int R0[5] = {0, 0, 1, 1, 2};
    const int R1[5] = {0, 1, 1, 2, 2};

    const int y0 = 2 * (ti + il), x0 = 2 * (tj + jl);
    float* ob = out + (((size_t)b * COUT + g * GC_) * 128 + y0) * 128 + x0;

#pragma unroll
    for (int c = 0; c < GC_; c++) {
        float n[3][3];
#pragma unroll
        for (int a = 0; a < 3; a++)
#pragma unroll
            for (int d = 0; d < 3; d++)
                n[a][d] = hs[c][il + a][jl + d];

        // packed column pairs np[r][kw] = (n[r][R0[kw]], n[r][R1[kw]])
        unsigned long long np[3][5];
#pragma unroll
        for (int r = 0; r < 3; r++) {
            np[r][0] = pk2(n[r][0], n[r][0]);
            np[r][1] = pk2(n[r][0], n[r][1]);
            np[r][2] = pk2(n[r][1], n[r][1]);
            np[r][3] = pk2(n[r][1], n[r][2]);
            np[r][4] = pk2(n[r][2], n[r][2]);
        }

        unsigned long long accA = 0ull;   // (a00, a01) — output row y0
        unsigned long long accB = 0ull;   // (a10, a11) — output row y0+1
#pragma unroll
        for (int kh = 0; kh < 5; kh++) {
            const int r0 = R0[kh], r1 = R1[kh];
#pragma unroll
            for (int kw = 0; kw < 5; kw++) {
                fma2(accA, wk2[kh * 5 + kw], np[r0][kw]);
                fma2(accB, wk2[kh * 5 + kw], np[r1][kw]);
            }
        }
        float a00, a01, a10, a11;
        upk2(accA, a00, a01);
        upk2(accB, a10, a11);
        *reinterpret_cast<float2*>(ob + (size_t)c * 16384)       = make_float2(a00, a01);
        *reinterpret_cast<float2*>(ob + (size_t)c * 16384 + 128) = make_float2(a10, a11);
    }
}

// ---------------------------------------------------------------------------
extern "C" void kernel_launch(void* const* d_in, const int* in_sizes, int n_in,
                              void* d_out, int out_size) {
    const float* x      = (const float*)d_in[0];
    const float* w1x1   = (const float*)d_in[1];
    const float* b1x1   = (const float*)d_in[2];
    const float* w_red  = (const float*)d_in[3];
    const float* b_red  = (const float*)d_in[4];
    const float* gamma  = (const float*)d_in[5];
    const float* beta   = (const float*)d_in[6];
    const float* mean   = (const float*)d_in[7];
    const float* var    = (const float*)d_in[8];
    const float* w_span = (const float*)d_in[9];
    const float* b_span = (const float*)d_in[10];
    float* out = (float*)d_out;

    conv1_k<<<dim3(PHALF / 128, 2, B_), 256>>>(x, w1x1, b1x1);
    kgen_k<<<dim3((B_ * PHALF) / 64, 1, 1), 256>>>(w_red, b_red, gamma, beta,
                                                   mean, var, w_span, b_span);
    inv_k<<<dim3(16, GROUPS, B_), 256>>>(out);
}

// round 10
// speedup vs baseline: 1.4157x; 1.1583x over previous
#include <cuda_runtime.h>
#include <cuda_bf16.h>
#include <cstdint>

// Shapes (fixed by the problem):
//   x:     [4, 256, 64, 64]
//   h:     [4, 128, 64, 64]   (half-res; h_up = 2x nearest upsample of h)
//   wgt:   [4, 200, 64, 64]   (kernel-gen branch at HALF res: constant over 2x2)
//   out:   [4, 128, 128, 128]
#define B_     4
#define CIN    256
#define COUT   128
#define HHALF  64
#define PHALF  4096        // 64*64
#define CRED   32
#define GROUPS 8
#define GC_    16
#define KK     25          // 5x5
#define SPAN   200         // KK*GROUPS

// Scratch (device globals; allocation inside kernel_launch is forbidden)
__device__ float g_h  [(size_t)B_ * COUT * PHALF];   // 8.4 MB
__device__ float g_wgt[(size_t)B_ * SPAN * PHALF];   // 13.1 MB
__device__ __nv_bfloat16 g_wh[COUT * CIN];           // w bf16 hi (o-major, k-contig)
__device__ __nv_bfloat16 g_wl[COUT * CIN];           // w bf16 lo residual

// ---- packed f32x2 helpers (per-lane identical to fmaf) ---------------------
__device__ __forceinline__ unsigned long long pk2(float a, float b) {
    unsigned long long r;
    asm("mov.b64 %0, {%1, %2};" : "=l"(r) : "f"(a), "f"(b));
    return r;
}
__device__ __forceinline__ void fma2(unsigned long long& d,
                                     unsigned long long a, unsigned long long b) {
    asm("fma.rn.f32x2 %0, %1, %2, %0;" : "+l"(d) : "l"(a), "l"(b));
}
__device__ __forceinline__ void upk2(unsigned long long v, float& lo, float& hi) {
    asm("mov.b64 {%0, %1}, %2;" : "=f"(lo), "=f"(hi) : "l"(v));
}

__device__ __forceinline__ uint32_t smem_u32(const void* p) {
    uint32_t a;
    asm("{ .reg .u64 t; cvta.to.shared.u64 t, %1; cvt.u32.u64 %0, t; }" : "=r"(a) : "l"(p));
    return a;
}
__device__ __forceinline__ void ldmx4(uint32_t* r, uint32_t addr) {
    asm volatile("ldmatrix.sync.aligned.m8n8.x4.shared.b16 {%0,%1,%2,%3}, [%4];"
                 : "=r"(r[0]), "=r"(r[1]), "=r"(r[2]), "=r"(r[3]) : "r"(addr));
}
__device__ __forceinline__ void ldmx2t(uint32_t* r, uint32_t addr) {
    asm volatile("ldmatrix.sync.aligned.m8n8.x2.trans.shared.b16 {%0,%1}, [%2];"
                 : "=r"(r[0]), "=r"(r[1]) : "r"(addr));
}
__device__ __forceinline__ void mma_bf16(float* d, const uint32_t* a, const uint32_t* b) {
    asm volatile(
        "mma.sync.aligned.m16n8k16.row.col.f32.bf16.bf16.f32 "
        "{%0,%1,%2,%3}, {%4,%5,%6,%7}, {%8,%9}, {%0,%1,%2,%3};"
        : "+f"(d[0]), "+f"(d[1]), "+f"(d[2]), "+f"(d[3])
        : "r"(a[0]), "r"(a[1]), "r"(a[2]), "r"(a[3]), "r"(b[0]), "r"(b[1]));
}

// ---------------------------------------------------------------------------
// convw_k: w1x1 fp32 [128][256] -> bf16 hi/lo split (o-major, k-contig)
// ---------------------------------------------------------------------------
__global__ __launch_bounds__(256) void convw_k(const float* __restrict__ w) {
    int i4 = blockIdx.x * 256 + threadIdx.x;           // 8192 quads
    float4 v = *(const float4*)(w + 4 * i4);
    float f[4] = {v.x, v.y, v.z, v.w};
    __nv_bfloat16 hi[4], lo[4];
#pragma unroll
    for (int j = 0; j < 4; j++) {
        hi[j] = __float2bfloat16(f[j]);
        lo[j] = __float2bfloat16(f[j] - __bfloat162float(hi[j]));
    }
    __nv_bfloat162* dh = (__nv_bfloat162*)(g_wh + 4 * i4);
    __nv_bfloat162* dl = (__nv_bfloat162*)(g_wl + 4 * i4);
    dh[0] = __halves2bfloat162(hi[0], hi[1]);
    dh[1] = __halves2bfloat162(hi[2], hi[3]);
    dl[0] = __halves2bfloat162(lo[0], lo[1]);
    dl[1] = __halves2bfloat162(lo[2], lo[3]);
}

// ---------------------------------------------------------------------------
// conv1_mma_k: h = conv1x1 via warp-level bf16 mma.sync (HMMA), fp32 accum.
// D[o=128][px=128] per CTA, K=256 fp32 split into bf16 (hi,lo):
//    D = Ah*Bh + Ah*Bl + Al*Bh   (Al*Bl dropped, ~2^-18 relative)
// A = w hi/lo, fully smem-resident [128][256] (row pad 528B -> ldmatrix
// conflict-free). B = x chunk, converted fp32->bf16 IN-KERNEL, natural [k][px]
// layout (row pad 272B), fragments via ldmatrix.x2.trans. 8 chunks of k=32,
// double-buffered with register prefetch. 8 warps, warp tile 64M x 32N.
// ---------------------------------------------------------------------------
static constexpr int SA_H   = 0;            // 128 rows * 528 B
static constexpr int SA_L   = 67584;
static constexpr int SB     = 135168;       // 4 * (32 rows * 272 B) : [buf][hl]
static constexpr int SB_SZ  = 8704;
static constexpr int SM_TOT = 135168 + 4 * SB_SZ;   // 169984 B

__global__ __launch_bounds__(256) void conv1_mma_k(const float* __restrict__ x,
                                                   const float* __restrict__ bias) {
    extern __shared__ char smem[];
    const uint32_t sbase = smem_u32(smem);
    const int tid  = threadIdx.x;
    const int wrp  = tid >> 5;
    const int lane = tid & 31;
    const int b    = blockIdx.y;
    const int p0   = blockIdx.x * 128;

    const int wm = (wrp & 1) * 64;         // warp M offset (o)
    const int wn = (wrp >> 1) * 32;        // warp N offset (px)

    // ---- load A (w hi/lo) into smem once: 4096 uint4 each ----
    {
        const uint4* sh = (const uint4*)g_wh;
        const uint4* sl = (const uint4*)g_wl;
        for (int u = tid; u < 4096; u += 256) {
            int row = u >> 5, c16 = u & 31;
            *(uint4*)(smem + SA_H + row * 528 + c16 * 16) = sh[u];
            *(uint4*)(smem + SA_L + row * 528 + c16 * 16) = sl[u];
        }
    }

    // ---- B prefetch chunk 0 (32 k-rows x 128 px fp32) ----
    const float* xb = x + (size_t)b * CIN * PHALF + p0;
    float4 xr[4];
#pragma unroll
    for (int i = 0; i < 4; i++) {
        int u = tid + i * 256;
        int row = u >> 5, seg = u & 31;
        xr[i] = ((const float4*)(xb + (size_t)row * PHALF))[seg];
    }

    float acc[4][4][4];                    // [mt][nt][frag]
#pragma unroll
    for (int i = 0; i < 4; i++)
#pragma unroll
        for (int j = 0; j < 4; j++)
#pragma unroll
            for (int q = 0; q < 4; q++) acc[i][j][q] = 0.f;

    for (int kc = 0; kc < 8; kc++) {
        const int buf = kc & 1;
        const uint32_t bh_base = sbase + SB + (buf * 2 + 0) * SB_SZ;
        const uint32_t bl_base = sbase + SB + (buf * 2 + 1) * SB_SZ;

        // convert + store prefetched chunk into smem (hi & lo)
#pragma unroll
        for (int i = 0; i < 4; i++) {
            int u = tid + i * 256;
            int row = u >> 5, seg = u & 31;
            float f[4] = {xr[i].x, xr[i].y, xr[i].z, xr[i].w};
            __nv_bfloat16 hi[4], lo[4];
#pragma unroll
            for (int j = 0; j < 4; j++) {
                hi[j] = __float2bfloat16(f[j]);
                lo[j] = __float2bfloat16(f[j] - __bfloat162float(hi[j]));
            }
            __nv_bfloat162 h2[2] = {__halves2bfloat162(hi[0], hi[1]),
                                    __halves2bfloat162(hi[2], hi[3])};
            __nv_bfloat162 l2[2] = {__halves2bfloat162(lo[0], lo[1]),
                                    __halves2bfloat162(lo[2], lo[3])};
            char* ph = smem + SB + (buf * 2 + 0) * SB_SZ + row * 272 + seg * 8;
            char* pl = smem + SB + (buf * 2 + 1) * SB_SZ + row * 272 + seg * 8;
            ((__nv_bfloat162*)ph)[0] = h2[0]; ((__nv_bfloat162*)ph)[1] = h2[1];
            ((__nv_bfloat162*)pl)[0] = l2[0]; ((__nv_bfloat162*)pl)[1] = l2[1];
        }
        __syncthreads();

        // prefetch next chunk (overlaps with mma below)
        if (kc < 7) {
#pragma unroll
            for (int i = 0; i < 4; i++) {
                int u = tid + i * 256;
                int row = u >> 5, seg = u & 31;
                xr[i] = ((const float4*)(xb + (size_t)((kc + 1) * 32 + row) * PHALF))[seg];
            }
        }

        // ---- mma over this chunk: 2 ksteps of 16 ----
#pragma unroll
        for (int s = 0; s < 2; s++) {
            // A fragments (hi & lo) for 4 M-tiles
            uint32_t a_h[4][4], a_l[4][4];
            const uint32_t akoff = (uint32_t)(kc * 64 + s * 32 + (lane >> 4) * 16);
#pragma unroll
            for (int mt = 0; mt < 4; mt++) {
                uint32_t arow = (uint32_t)(wm + mt * 16 + (lane & 15));
                ldmx4(a_h[mt], sbase + SA_H + arow * 528 + akoff);
                ldmx4(a_l[mt], sbase + SA_L + arow * 528 + akoff);
            }
            // B fragments (hi & lo) for 4 N-tiles
            uint32_t b_h[4][2], b_l[4][2];
            const uint32_t brow = (uint32_t)(s * 16 + (lane & 15));
#pragma unroll
            for (int nt = 0; nt < 4; nt++) {
                uint32_t bcol = (uint32_t)((wn + nt * 8) * 2);
                ldmx2t(b_h[nt], bh_base + brow * 272 + bcol);
                ldmx2t(b_l[nt], bl_base + brow * 272 + bcol);
            }
#pragma unroll
            for (int mt = 0; mt < 4; mt++)
#pragma unroll
                for (int nt = 0; nt < 4; nt++) {
                    mma_bf16(acc[mt][nt], a_h[mt], b_h[nt]);
                    mma_bf16(acc[mt][nt], a_h[mt], b_l[nt]);
                    mma_bf16(acc[mt][nt], a_l[mt], b_h[nt]);
                }
        }
        __syncthreads();
    }

    // ---- epilogue: bias + store ----
#pragma unroll
    for (int mt = 0; mt < 4; mt++) {
        int o0 = wm + mt * 16 + (lane >> 2);
        float bv0 = bias[o0];
        float bv1 = bias[o0 + 8];
#pragma unroll
        for (int nt = 0; nt < 4; nt++) {
            int px = p0 + wn + nt * 8 + (lane & 3) * 2;
            float* d0 = g_h + ((size_t)b * COUT + o0) * PHALF + px;
            float* d1 = g_h + ((size_t)b * COUT + o0 + 8) * PHALF + px;
            *(float2*)d0 = make_float2(acc[mt][nt][0] + bv0, acc[mt][nt][1] + bv0);
            *(float2*)d1 = make_float2(acc[mt][nt][2] + bv1, acc[mt][nt][3] + bv1);
        }
    }
}

// ---------------------------------------------------------------------------
// Kernel 2: kernel-generation branch AT HALF RES (unchanged from R7/R8).
// ---------------------------------------------------------------------------
__global__ __launch_bounds__(256) void kgen_k(const float* __restrict__ wred,
                                              const float* __restrict__ bred,
                                              const float* __restrict__ gamma,
                                              const float* __restrict__ beta,
                                              const float* __restrict__ mean,
                                              const float* __restrict__ var,
                                              const float* __restrict__ wspan,
                                              const float* __restrict__ bspan) {
    __shared__ float pool[6600];
    __shared__ float h_sh[16][64];
    __shared__ float r_sh[CRED][68];

    const int tid = threadIdx.x;
    const int q0  = blockIdx.x * 64;
    const int b   = q0 >> 12;
    const int p0  = q0 & 4095;

    for (int i = tid; i < CRED * COUT; i += 256) {
        int o = i >> 7, c = i & 127;
        pool[c * CRED + o] = wred[i];
    }

    const int oq  = tid >> 5;
    const int pxp = tid & 31;

    float acc[4][2];
#pragma unroll
    for (int i = 0; i < 4; i++) {
        float bv = bred[4 * oq + i];
        acc[i][0] = bv; acc[i][1] = bv;
    }

    const float* hb = g_h + (size_t)b * COUT * PHALF + p0;
    const int hc = tid >> 4, hp4 = tid & 15;

    for (int cc = 0; cc < COUT; cc += 16) {
        __syncthreads();
        *(float4*)&h_sh[hc][4 * hp4] =
            *(const float4*)(hb + (size_t)(cc + hc) * PHALF + 4 * hp4);
        __syncthreads();
#pragma unroll
        for (int c = 0; c < 16; c++) {
            float4 wv = *(const float4*)&pool[(cc + c) * CRED + 4 * oq];
            float2 hv = *(const float2*)&h_sh[c][2 * pxp];
            acc[0][0] += wv.x * hv.x;  acc[0][1] += wv.x * hv.y;
            acc[1][0] += wv.y * hv.x;  acc[1][1] += wv.y * hv.y;
            acc[2][0] += wv.z * hv.x;  acc[2][1] += wv.z * hv.y;
            acc[3][0] += wv.w * hv.x;  acc[3][1] += wv.w * hv.y;
        }
    }

#pragma unroll
    for (int i = 0; i < 4; i++) {
        int o = 4 * oq + i;
        float sc = gamma[o] * rsqrtf(var[o] + 1e-5f);
        float sh = beta[o] - mean[o] * sc;
        float v0 = fmaxf(acc[i][0] * sc + sh, 0.f);
        float v1 = fmaxf(acc[i][1] * sc + sh, 0.f);
        *(float2*)&r_sh[o][2 * pxp] = make_float2(v0, v1);
    }
    __syncthreads();

    for (int i = tid; i < SPAN * CRED; i += 256) {
        int s = i >> 5, oo = i & 31;
        pool[s * 33 + oo] = wspan[i];
    }
    __syncthreads();

    if (tid < 200) {
        const int s0 = (tid >> 3) * 8;
        const int px = (tid & 7) * 8;

        float acc2[8][8];
#pragma unroll
        for (int i = 0; i < 8; i++) {
            float bv = bspan[s0 + i];
#pragma unroll
            for (int j = 0; j < 8; j++) acc2[i][j] = bv;
        }

#pragma unroll 4
        for (int oo = 0; oo < CRED; oo++) {
            float w8[8];
#pragma unroll
            for (int i = 0; i < 8; i++) w8[i] = pool[(s0 + i) * 33 + oo];
            float4 ra = *(const float4*)&r_sh[oo][px];
            float4 rb = *(const float4*)&r_sh[oo][px + 4];
#pragma unroll
            for (int i = 0; i < 8; i++) {
                acc2[i][0] += w8[i] * ra.x;  acc2[i][1] += w8[i] * ra.y;
                acc2[i][2] += w8[i] * ra.z;  acc2[i][3] += w8[i] * ra.w;
                acc2[i][4] += w8[i] * rb.x;  acc2[i][5] += w8[i] * rb.y;
                acc2[i][6] += w8[i] * rb.z;  acc2[i][7] += w8[i] * rb.w;
            }
        }

        float* wb = g_wgt + (size_t)b * SPAN * PHALF + p0 + px;
#pragma unroll
        for (int i = 0; i < 8; i++) {
            float4 v0 = make_float4(acc2[i][0], acc2[i][1], acc2[i][2], acc2[i][3]);
            float4 v1 = make_float4(acc2[i][4], acc2[i][5], acc2[i][6], acc2[i][7]);
            *(float4*)(wb + (size_t)(s0 + i) * PHALF)     = v0;
            *(float4*)(wb + (size_t)(s0 + i) * PHALF + 4) = v1;
        }
    }
}

// ---------------------------------------------------------------------------
// Kernel 3: involution at full res, packed f32x2 math (unchanged from R8).
// ---------------------------------------------------------------------------
__global__ __launch_bounds__(256) void inv_k(float* __restrict__ out) {
    __shared__ float hs[GC_][18][19];

    const int b = blockIdx.z;
    const int g = blockIdx.y;
    const int ti = (blockIdx.x >> 2) * 16;
    const int tj = (blockIdx.x & 3) * 16;
    const int tid = threadIdx.x;

    const float* hb = g_h + ((size_t)b * COUT + g * GC_) * PHALF;
    for (int e = tid; e < GC_ * 18 * 18; e += 256) {
        int c   = e / 324;
        int rem = e - c * 324;
        int rr  = rem / 18, cc = rem - rr * 18;
        int gi = ti - 1 + rr, gj = tj - 1 + cc;
        float v = 0.f;
        if ((unsigned)gi < 64u && (unsigned)gj < 64u)
            v = hb[(size_t)c * PHALF + gi * HHALF + gj];
        hs[c][rr][cc] = v;
    }

    const int jl = tid & 15, il = tid >> 4;
    const int pix = (ti + il) * HHALF + (tj + jl);

    unsigned long long wk2[KK];
    {
        const float* wgp = g_wgt + ((size_t)b * SPAN + g * KK) * PHALF + pix;
#pragma unroll
        for (int k = 0; k < KK; k++) {
            float wv = wgp[(size_t)k * PHALF];
            wk2[k] = pk2(wv, wv);
        }
    }

    __syncthreads();

    const int R0[5] = {0, 0, 1, 1, 2};
    const int R1[5] = {0, 1, 1, 2, 2};

    const int y0 = 2 * (ti + il), x0 = 2 * (tj + jl);
    float* ob = out + (((size_t)b * COUT + g * GC_) * 128 + y0) * 128 + x0;

#pragma unroll
    for (int c = 0; c < GC_; c++) {
        float n[3][3];
#pragma unroll
        for (int a = 0; a < 3; a++)
#pragma unroll
            for (int d = 0; d < 3; d++)
                n[a][d] = hs[c][il + a][jl + d];

        unsigned long long np[3][5];
#pragma unroll
        for (int r = 0; r < 3; r++) {
            np[r][0] = pk2(n[r][0], n[r][0]);
            np[r][1] = pk2(n[r][0], n[r][1]);
            np[r][2] = pk2(n[r][1], n[r][1]);
            np[r][3] = pk2(n[r][1], n[r][2]);
            np[r][4] = pk2(n[r][2], n[r][2]);
        }

        unsigned long long accA = 0ull;
        unsigned long long accB = 0ull;
#pragma unroll
        for (int kh = 0; kh < 5; kh++) {
            const int r0 = R0[kh], r1 = R1[kh];
#pragma unroll
            for (int kw = 0; kw < 5; kw++) {
                fma2(accA, wk2[kh * 5 + kw], np[r0][kw]);
                fma2(accB, wk2[kh * 5 + kw], np[r1][kw]);
            }
        }
        float a00, a01, a10, a11;
        upk2(accA, a00, a01);
        upk2(accB, a10, a11);
        *reinterpret_cast<float2*>(ob + (size_t)c * 16384)       = make_float2(a00, a01);
        *reinterpret_cast<float2*>(ob + (size_t)c * 16384 + 128) = make_float2(a10, a11);
    }
}

// ---------------------------------------------------------------------------
extern "C" void kernel_launch(void* const* d_in, const int* in_sizes, int n_in,
                              void* d_out, int out_size) {
    const float* x      = (const float*)d_in[0];
    const float* w1x1   = (const float*)d_in[1];
    const float* b1x1   = (const float*)d_in[2];
    const float* w_red  = (const float*)d_in[3];
    const float* b_red  = (const float*)d_in[4];
    const float* gamma  = (const float*)d_in[5];
    const float* beta   = (const float*)d_in[6];
    const float* mean   = (const float*)d_in[7];
    const float* var    = (const float*)d_in[8];
    const float* w_span = (const float*)d_in[9];
    const float* b_span = (const float*)d_in[10];
    float* out = (float*)d_out;

    cudaFuncSetAttribute(conv1_mma_k,
                         cudaFuncAttributeMaxDynamicSharedMemorySize, SM_TOT);

    convw_k<<<32, 256>>>(w1x1);
    conv1_mma_k<<<dim3(PHALF / 128, B_), 256, SM_TOT>>>(x, b1x1);
    kgen_k<<<dim3((B_ * PHALF) / 64, 1, 1), 256>>>(w_red, b_red, gamma, beta,
                                                   mean, var, w_span, b_span);
    inv_k<<<dim3(16, GROUPS, B_), 256>>>(out);
}

// round 11
// speedup vs baseline: 1.4663x; 1.0357x over previous
#include <cuda_runtime.h>
#include <cuda_bf16.h>
#include <cstdint>

// Shapes (fixed by the problem):
//   x:     [4, 256, 64, 64]
//   h:     [4, 128, 64, 64]   (half-res; h_up = 2x nearest upsample of h)
//   wgt:   [4, 200, 64, 64]   (kernel-gen branch at HALF res: constant over 2x2)
//   out:   [4, 128, 128, 128]
#define B_     4
#define CIN    256
#define COUT   128
#define HHALF  64
#define PHALF  4096        // 64*64
#define CRED   32
#define GROUPS 8
#define GC_    16
#define KK     25          // 5x5
#define SPAN   200         // KK*GROUPS

// Scratch (device globals; allocation inside kernel_launch is forbidden)
__device__ float g_h  [(size_t)B_ * COUT * PHALF];   // 8.4 MB
__device__ float g_wgt[(size_t)B_ * SPAN * PHALF];   // 13.1 MB
__device__ __nv_bfloat16 g_wh[COUT * CIN];           // w bf16 hi (o-major, k-contig)
__device__ __nv_bfloat16 g_wl[COUT * CIN];           // w bf16 lo residual

// ---- packed f32x2 helpers (per-lane identical to fmaf) ---------------------
__device__ __forceinline__ unsigned long long pk2(float a, float b) {
    unsigned long long r;
    asm("mov.b64 %0, {%1, %2};" : "=l"(r) : "f"(a), "f"(b));
    return r;
}
__device__ __forceinline__ void fma2(unsigned long long& d,
                                     unsigned long long a, unsigned long long b) {
    asm("fma.rn.f32x2 %0, %1, %2, %0;" : "+l"(d) : "l"(a), "l"(b));
}
__device__ __forceinline__ void upk2(unsigned long long v, float& lo, float& hi) {
    asm("mov.b64 {%0, %1}, %2;" : "=f"(lo), "=f"(hi) : "l"(v));
}

__device__ __forceinline__ uint32_t smem_u32(const void* p) {
    uint32_t a;
    asm("{ .reg .u64 t; cvta.to.shared.u64 t, %1; cvt.u32.u64 %0, t; }" : "=r"(a) : "l"(p));
    return a;
}
__device__ __forceinline__ void ldmx4(uint32_t* r, uint32_t addr) {
    asm volatile("ldmatrix.sync.aligned.m8n8.x4.shared.b16 {%0,%1,%2,%3}, [%4];"
                 : "=r"(r[0]), "=r"(r[1]), "=r"(r[2]), "=r"(r[3]) : "r"(addr));
}
__device__ __forceinline__ void ldmx2t(uint32_t* r, uint32_t addr) {
    asm volatile("ldmatrix.sync.aligned.m8n8.x2.trans.shared.b16 {%0,%1}, [%2];"
                 : "=r"(r[0]), "=r"(r[1]) : "r"(addr));
}
__device__ __forceinline__ void mma_bf16(float* d, const uint32_t* a, const uint32_t* b) {
    asm volatile(
        "mma.sync.aligned.m16n8k16.row.col.f32.bf16.bf16.f32 "
        "{%0,%1,%2,%3}, {%4,%5,%6,%7}, {%8,%9}, {%0,%1,%2,%3};"
        : "+f"(d[0]), "+f"(d[1]), "+f"(d[2]), "+f"(d[3])
        : "r"(a[0]), "r"(a[1]), "r"(a[2]), "r"(a[3]), "r"(b[0]), "r"(b[1]));
}

// ---------------------------------------------------------------------------
// convw_k: w1x1 fp32 [128][256] -> bf16 hi/lo split (o-major, k-contig)
// ---------------------------------------------------------------------------
__global__ __launch_bounds__(256) void convw_k(const float* __restrict__ w) {
    int i4 = blockIdx.x * 256 + threadIdx.x;           // 8192 quads
    float4 v = *(const float4*)(w + 4 * i4);
    float f[4] = {v.x, v.y, v.z, v.w};
    __nv_bfloat16 hi[4], lo[4];
#pragma unroll
    for (int j = 0; j < 4; j++) {
        hi[j] = __float2bfloat16(f[j]);
        lo[j] = __float2bfloat16(f[j] - __bfloat162float(hi[j]));
    }
    __nv_bfloat162* dh = (__nv_bfloat162*)(g_wh + 4 * i4);
    __nv_bfloat162* dl = (__nv_bfloat162*)(g_wl + 4 * i4);
    dh[0] = __halves2bfloat162(hi[0], hi[1]);
    dh[1] = __halves2bfloat162(hi[2], hi[3]);
    dl[0] = __halves2bfloat162(lo[0], lo[1]);
    dl[1] = __halves2bfloat162(lo[2], lo[3]);
}

// ---------------------------------------------------------------------------
// conv1_mma_k: h = conv1x1 via warp-level bf16 mma.sync (HMMA), fp32 accum.
// D[o=128][px=128] per CTA, K=256 fp32 split into bf16 (hi,lo):
//    D = Ah*Bh + Ah*Bl + Al*Bh   (Al*Bl dropped, ~2^-18 relative)
// (unchanged from R10)
// ---------------------------------------------------------------------------
static constexpr int SA_H   = 0;            // 128 rows * 528 B
static constexpr int SA_L   = 67584;
static constexpr int SB     = 135168;       // 4 * (32 rows * 272 B) : [buf][hl]
static constexpr int SB_SZ  = 8704;
static constexpr int SM_TOT = 135168 + 4 * SB_SZ;   // 169984 B

__global__ __launch_bounds__(256) void conv1_mma_k(const float* __restrict__ x,
                                                   const float* __restrict__ bias) {
    extern __shared__ char smem[];
    const uint32_t sbase = smem_u32(smem);
    const int tid  = threadIdx.x;
    const int wrp  = tid >> 5;
    const int lane = tid & 31;
    const int b    = blockIdx.y;
    const int p0   = blockIdx.x * 128;

    const int wm = (wrp & 1) * 64;         // warp M offset (o)
    const int wn = (wrp >> 1) * 32;        // warp N offset (px)

    // ---- load A (w hi/lo) into smem once: 4096 uint4 each ----
    {
        const uint4* sh = (const uint4*)g_wh;
        const uint4* sl = (const uint4*)g_wl;
        for (int u = tid; u < 4096; u += 256) {
            int row = u >> 5, c16 = u & 31;
            *(uint4*)(smem + SA_H + row * 528 + c16 * 16) = sh[u];
            *(uint4*)(smem + SA_L + row * 528 + c16 * 16) = sl[u];
        }
    }

    // ---- B prefetch chunk 0 (32 k-rows x 128 px fp32) ----
    const float* xb = x + (size_t)b * CIN * PHALF + p0;
    float4 xr[4];
#pragma unroll
    for (int i = 0; i < 4; i++) {
        int u = tid + i * 256;
        int row = u >> 5, seg = u & 31;
        xr[i] = ((const float4*)(xb + (size_t)row * PHALF))[seg];
    }

    float acc[4][4][4];                    // [mt][nt][frag]
#pragma unroll
    for (int i = 0; i < 4; i++)
#pragma unroll
        for (int j = 0; j < 4; j++)
#pragma unroll
            for (int q = 0; q < 4; q++) acc[i][j][q] = 0.f;

    for (int kc = 0; kc < 8; kc++) {
        const int buf = kc & 1;
        const uint32_t bh_base = sbase + SB + (buf * 2 + 0) * SB_SZ;
        const uint32_t bl_base = sbase + SB + (buf * 2 + 1) * SB_SZ;

        // convert + store prefetched chunk into smem (hi & lo)
#pragma unroll
        for (int i = 0; i < 4; i++) {
            int u = tid + i * 256;
            int row = u >> 5, seg = u & 31;
            float f[4] = {xr[i].x, xr[i].y, xr[i].z, xr[i].w};
            __nv_bfloat16 hi[4], lo[4];
#pragma unroll
            for (int j = 0; j < 4; j++) {
                hi[j] = __float2bfloat16(f[j]);
                lo[j] = __float2bfloat16(f[j] - __bfloat162float(hi[j]));
            }
            __nv_bfloat162 h2[2] = {__halves2bfloat162(hi[0], hi[1]),
                                    __halves2bfloat162(hi[2], hi[3])};
            __nv_bfloat162 l2[2] = {__halves2bfloat162(lo[0], lo[1]),
                                    __halves2bfloat162(lo[2], lo[3])};
            char* ph = smem + SB + (buf * 2 + 0) * SB_SZ + row * 272 + seg * 8;
            char* pl = smem + SB + (buf * 2 + 1) * SB_SZ + row * 272 + seg * 8;
            ((__nv_bfloat162*)ph)[0] = h2[0]; ((__nv_bfloat162*)ph)[1] = h2[1];
            ((__nv_bfloat162*)pl)[0] = l2[0]; ((__nv_bfloat162*)pl)[1] = l2[1];
        }
        __syncthreads();

        // prefetch next chunk (overlaps with mma below)
        if (kc < 7) {
#pragma unroll
            for (int i = 0; i < 4; i++) {
                int u = tid + i * 256;
                int row = u >> 5, seg = u & 31;
                xr[i] = ((const float4*)(xb + (size_t)((kc + 1) * 32 + row) * PHALF))[seg];
            }
        }

        // ---- mma over this chunk: 2 ksteps of 16 ----
#pragma unroll
        for (int s = 0; s < 2; s++) {
            uint32_t a_h[4][4], a_l[4][4];
            const uint32_t akoff = (uint32_t)(kc * 64 + s * 32 + (lane >> 4) * 16);
#pragma unroll
            for (int mt = 0; mt < 4; mt++) {
                uint32_t arow = (uint32_t)(wm + mt * 16 + (lane & 15));
                ldmx4(a_h[mt], sbase + SA_H + arow * 528 + akoff);
                ldmx4(a_l[mt], sbase + SA_L + arow * 528 + akoff);
            }
            uint32_t b_h[4][2], b_l[4][2];
            const uint32_t brow = (uint32_t)(s * 16 + (lane & 15));
#pragma unroll
            for (int nt = 0; nt < 4; nt++) {
                uint32_t bcol = (uint32_t)((wn + nt * 8) * 2);
                ldmx2t(b_h[nt], bh_base + brow * 272 + bcol);
                ldmx2t(b_l[nt], bl_base + brow * 272 + bcol);
            }
#pragma unroll
            for (int mt = 0; mt < 4; mt++)
#pragma unroll
                for (int nt = 0; nt < 4; nt++) {
                    mma_bf16(acc[mt][nt], a_h[mt], b_h[nt]);
                    mma_bf16(acc[mt][nt], a_h[mt], b_l[nt]);
                    mma_bf16(acc[mt][nt], a_l[mt], b_h[nt]);
                }
        }
        __syncthreads();
    }

    // ---- epilogue: bias + store ----
#pragma unroll
    for (int mt = 0; mt < 4; mt++) {
        int o0 = wm + mt * 16 + (lane >> 2);
        float bv0 = bias[o0];
        float bv1 = bias[o0 + 8];
#pragma unroll
        for (int nt = 0; nt < 4; nt++) {
            int px = p0 + wn + nt * 8 + (lane & 3) * 2;
            float* d0 = g_h + ((size_t)b * COUT + o0) * PHALF + px;
            float* d1 = g_h + ((size_t)b * COUT + o0 + 8) * PHALF + px;
            *(float2*)d0 = make_float2(acc[mt][nt][0] + bv0, acc[mt][nt][1] + bv0);
            *(float2*)d1 = make_float2(acc[mt][nt][2] + bv1, acc[mt][nt][3] + bv1);
        }
    }
}

// ---------------------------------------------------------------------------
// Kernel 2: kernel-generation branch AT HALF RES (unchanged from R7/R8).
// ---------------------------------------------------------------------------
__global__ __launch_bounds__(256) void kgen_k(const float* __restrict__ wred,
                                              const float* __restrict__ bred,
                                              const float* __restrict__ gamma,
                                              const float* __restrict__ beta,
                                              const float* __restrict__ mean,
                                              const float* __restrict__ var,
                                              const float* __restrict__ wspan,
                                              const float* __restrict__ bspan) {
    __shared__ float pool[6600];
    __shared__ float h_sh[16][64];
    __shared__ float r_sh[CRED][68];

    const int tid = threadIdx.x;
    const int q0  = blockIdx.x * 64;
    const int b   = q0 >> 12;
    const int p0  = q0 & 4095;

    for (int i = tid; i < CRED * COUT; i += 256) {
        int o = i >> 7, c = i & 127;
        pool[c * CRED + o] = wred[i];
    }

    const int oq  = tid >> 5;
    const int pxp = tid & 31;

    float acc[4][2];
#pragma unroll
    for (int i = 0; i < 4; i++) {
        float bv = bred[4 * oq + i];
        acc[i][0] = bv; acc[i][1] = bv;
    }

    const float* hb = g_h + (size_t)b * COUT * PHALF + p0;
    const int hc = tid >> 4, hp4 = tid & 15;

    for (int cc = 0; cc < COUT; cc += 16) {
        __syncthreads();
        *(float4*)&h_sh[hc][4 * hp4] =
            *(const float4*)(hb + (size_t)(cc + hc) * PHALF + 4 * hp4);
        __syncthreads();
#pragma unroll
        for (int c = 0; c < 16; c++) {
            float4 wv = *(const float4*)&pool[(cc + c) * CRED + 4 * oq];
            float2 hv = *(const float2*)&h_sh[c][2 * pxp];
            acc[0][0] += wv.x * hv.x;  acc[0][1] += wv.x * hv.y;
            acc[1][0] += wv.y * hv.x;  acc[1][1] += wv.y * hv.y;
            acc[2][0] += wv.z * hv.x;  acc[2][1] += wv.z * hv.y;
            acc[3][0] += wv.w * hv.x;  acc[3][1] += wv.w * hv.y;
        }
    }

#pragma unroll
    for (int i = 0; i < 4; i++) {
        int o = 4 * oq + i;
        float sc = gamma[o] * rsqrtf(var[o] + 1e-5f);
        float sh = beta[o] - mean[o] * sc;
        float v0 = fmaxf(acc[i][0] * sc + sh, 0.f);
        float v1 = fmaxf(acc[i][1] * sc + sh, 0.f);
        *(float2*)&r_sh[o][2 * pxp] = make_float2(v0, v1);
    }
    __syncthreads();

    for (int i = tid; i < SPAN * CRED; i += 256) {
        int s = i >> 5, oo = i & 31;
        pool[s * 33 + oo] = wspan[i];
    }
    __syncthreads();

    if (tid < 200) {
        const int s0 = (tid >> 3) * 8;
        const int px = (tid & 7) * 8;

        float acc2[8][8];
#pragma unroll
        for (int i = 0; i < 8; i++) {
            float bv = bspan[s0 + i];
#pragma unroll
            for (int j = 0; j < 8; j++) acc2[i][j] = bv;
        }

#pragma unroll 4
        for (int oo = 0; oo < CRED; oo++) {
            float w8[8];
#pragma unroll
            for (int i = 0; i < 8; i++) w8[i] = pool[(s0 + i) * 33 + oo];
            float4 ra = *(const float4*)&r_sh[oo][px];
            float4 rb = *(const float4*)&r_sh[oo][px + 4];
#pragma unroll
            for (int i = 0; i < 8; i++) {
                acc2[i][0] += w8[i] * ra.x;  acc2[i][1] += w8[i] * ra.y;
                acc2[i][2] += w8[i] * ra.z;  acc2[i][3] += w8[i] * ra.w;
                acc2[i][4] += w8[i] * rb.x;  acc2[i][5] += w8[i] * rb.y;
                acc2[i][6] += w8[i] * rb.z;  acc2[i][7] += w8[i] * rb.w;
            }
        }

        float* wb = g_wgt + (size_t)b * SPAN * PHALF + p0 + px;
#pragma unroll
        for (int i = 0; i < 8; i++) {
            float4 v0 = make_float4(acc2[i][0], acc2[i][1], acc2[i][2], acc2[i][3]);
            float4 v1 = make_float4(acc2[i][4], acc2[i][5], acc2[i][6], acc2[i][7]);
            *(float4*)(wb + (size_t)(s0 + i) * PHALF)     = v0;
            *(float4*)(wb + (size_t)(s0 + i) * PHALF + 4) = v1;
        }
    }
}

// ---------------------------------------------------------------------------
// Kernel 3 (v3): involution with pre-collapsed 3x3 weights.
// The 5x5->3x3 index maps are fixed per sub-pixel, so collapse the 25 weights
// ONCE per thread into four 3x3 kernels (W00,W01,W10,W11), packed as f32x2
// pairs (W00,W01) / (W10,W11). The h tile is stored DUPLICATED as float2 so
// each (n,n) broadcast pair is a single LDS.64.
// Per channel: 9 LDS.64 + 18 fma2 (was 15 pk2 + 50 fma2).
// ---------------------------------------------------------------------------
__global__ __launch_bounds__(256) void inv_k(float* __restrict__ out) {
    __shared__ float2 hs[GC_][18][19];   // duplicated halo'd h tile, ~43.8 KB

    const int b = blockIdx.z;
    const int g = blockIdx.y;
    const int ti = (blockIdx.x >> 2) * 16;
    const int tj = (blockIdx.x & 3) * 16;
    const int tid = threadIdx.x;

    // load h tile (+1 halo each side) duplicated, with zero pad
    const float* hb = g_h + ((size_t)b * COUT + g * GC_) * PHALF;
    for (int e = tid; e < GC_ * 18 * 18; e += 256) {
        int c   = e / 324;
        int rem = e - c * 324;
        int rr  = rem / 18, cc = rem - rr * 18;
        int gi = ti - 1 + rr, gj = tj - 1 + cc;
        float v = 0.f;
        if ((unsigned)gi < 64u && (unsigned)gj < 64u)
            v = hb[(size_t)c * PHALF + gi * HHALF + gj];
        hs[c][rr][cc] = make_float2(v, v);
    }

    const int jl = tid & 15, il = tid >> 4;
    const int pix = (ti + il) * HHALF + (tj + jl);

    // ---- load 25 weights, collapse to 4 effective 3x3 kernels, pack ----
    unsigned long long wA[9], wB[9];     // (W00,W01) and (W10,W11)
    {
        float wk[KK];
        const float* wgp = g_wgt + ((size_t)b * SPAN + g * KK) * PHALF + pix;
#pragma unroll
        for (int k = 0; k < KK; k++) wk[k] = wgp[(size_t)k * PHALF];

        // row partials: P0[r][kw] over kh with R0[kh]=r; P1 with R1[kh]=r
        float P0[3][5], P1[3][5];
#pragma unroll
        for (int kw = 0; kw < 5; kw++) {
            P0[0][kw] = wk[0 + kw] + wk[5 + kw];
            P0[1][kw] = wk[10 + kw] + wk[15 + kw];
            P0[2][kw] = wk[20 + kw];
            P1[0][kw] = wk[0 + kw];
            P1[1][kw] = wk[5 + kw] + wk[10 + kw];
            P1[2][kw] = wk[15 + kw] + wk[20 + kw];
        }
#pragma unroll
        for (int r = 0; r < 3; r++) {
            float w00_0 = P0[r][0] + P0[r][1];
            float w00_1 = P0[r][2] + P0[r][3];
            float w00_2 = P0[r][4];
            float w01_0 = P0[r][0];
            float w01_1 = P0[r][1] + P0[r][2];
            float w01_2 = P0[r][3] + P0[r][4];
            float w10_0 = P1[r][0] + P1[r][1];
            float w10_1 = P1[r][2] + P1[r][3];
            float w10_2 = P1[r][4];
            float w11_0 = P1[r][0];
            float w11_1 = P1[r][1] + P1[r][2];
            float w11_2 = P1[r][3] + P1[r][4];
            wA[r * 3 + 0] = pk2(w00_0, w01_0);
            wA[r * 3 + 1] = pk2(w00_1, w01_1);
            wA[r * 3 + 2] = pk2(w00_2, w01_2);
            wB[r * 3 + 0] = pk2(w10_0, w11_0);
            wB[r * 3 + 1] = pk2(w10_1, w11_1);
            wB[r * 3 + 2] = pk2(w10_2, w11_2);
        }
    }

    __syncthreads();

    const int y0 = 2 * (ti + il), x0 = 2 * (tj + jl);
    float* ob = out + (((size_t)b * COUT + g * GC_) * 128 + y0) * 128 + x0;

#pragma unroll
    for (int c = 0; c < GC_; c++) {
        unsigned long long m[9];         // duplicated (n,n) pairs, LDS.64 each
#pragma unroll
        for (int a = 0; a < 3; a++)
#pragma unroll
            for (int d = 0; d < 3; d++)
                m[a * 3 + d] = *(const unsigned long long*)&hs[c][il + a][jl + d];

        unsigned long long accA = 0ull;  // (a00, a01)
        unsigned long long accB = 0ull;  // (a10, a11)
#pragma unroll
        for (int i = 0; i < 9; i++) {
            fma2(accA, wA[i], m[i]);
            fma2(accB, wB[i], m[i]);
        }
        float a00, a01, a10, a11;
        upk2(accA, a00, a01);
        upk2(accB, a10, a11);
        *reinterpret_cast<float2*>(ob + (size_t)c * 16384)       = make_float2(a00, a01);
        *reinterpret_cast<float2*>(ob + (size_t)c * 16384 + 128) = make_float2(a10, a11);
    }
}

// ---------------------------------------------------------------------------
extern "C" void kernel_launch(void* const* d_in, const int* in_sizes, int n_in,
                              void* d_out, int out_size) {
    const float* x      = (const float*)d_in[0];
    const float* w1x1   = (const float*)d_in[1];
    const float* b1x1   = (const float*)d_in[2];
    const float* w_red  = (const float*)d_in[3];
    const float* b_red  = (const float*)d_in[4];
    const float* gamma  = (const float*)d_in[5];
    const float* beta   = (const float*)d_in[6];
    const float* mean   = (const float*)d_in[7];
    const float* var    = (const float*)d_in[8];
    const float* w_span = (const float*)d_in[9];
    const float* b_span = (const float*)d_in[10];
    float* out = (float*)d_out;

    cudaFuncSetAttribute(conv1_mma_k,
                         cudaFuncAttributeMaxDynamicSharedMemorySize, SM_TOT);

    convw_k<<<32, 256>>>(w1x1);
    conv1_mma_k<<<dim3(PHALF / 128, B_), 256, SM_TOT>>>(x, b1x1);
    kgen_k<<<dim3((B_ * PHALF) / 64, 1, 1), 256>>>(w_red, b_red, gamma, beta,
                                                   mean, var, w_span, b_span);
    inv_k<<<dim3(16, GROUPS, B_), 256>>>(out);
}